// round 4
// baseline (speedup 1.0000x reference)
#include <cuda_runtime.h>
#include <cuda_bf16.h>
#include <stdint.h>

// ---------------- problem dims ----------------
#define BATCH 8
#define CIN   2
#define HH    64
#define WW    64
#define TT    200
#define NCH   7      // ceil(200/32) chunks of 32 timesteps (tail garbage is causal-safe)
#define C1    8
#define C2    8

// fp32 correctly-rounded decay constants
#define D1 0.36787944117144233f   // exp(-1)    : tau=1 (psp1, ref1)
#define D2 0.60653065971263342f   // exp(-1/2)  : tau=2 (psp2, ref2)
#define D3 0.77880078307140487f   // exp(-1/4)  : tau=4 (psp3, ref3)

// t-split: seg0 = chunks [0,4), seg1 = chunks [4,7) with warmup from chunk 2
#define SEG0_END   4
#define WARM_BEG   2

// ---------------- bit-packed intermediates ----------------
// layout: [b][chunk][c][h][w], one uint32 = 32 consecutive timesteps
__device__ uint32_t g_xbits[BATCH * NCH * CIN * HH * WW];  // 1.75 MB
__device__ uint32_t g_s1  [BATCH * NCH * C1  * HH * WW];   // 7 MB
__device__ uint32_t g_s2  [BATCH * NCH * C2  * HH * WW];   // 7 MB

// =====================================================================
// K0: binarize + time-transpose input [b,c,h,w,t] -> bitmasks
// =====================================================================
__global__ void k_binarize(const float* __restrict__ x) {
    int tid = blockIdx.x * blockDim.x + threadIdx.x;
    if (tid >= BATCH * CIN * HH * WW * NCH) return;
    int k   = tid % NCH;
    int pix = tid / NCH;                  // (b*CIN+c)*HH*WW + h*WW + w
    int w = pix % WW; int t1 = pix / WW;
    int h = t1 % HH;  t1 /= HH;
    int c = t1 % CIN; int b = t1 / CIN;
    const float* p = x + (size_t)pix * TT + k * 32;
    int n = min(32, TT - k * 32);
    uint32_t bits = 0;
    for (int i = 0; i < n; i++) bits |= (p[i] > 0.5f) ? (1u << i) : 0u;
    g_xbits[(((b * NCH + k) * CIN + c) * HH + h) * WW + w] = bits;
}

// =====================================================================
// K1: layer 1.  u = IIR_1(conv5x5(xbits)); spike(th=30, dref=D1)
// grid = 256 pixblocks x 4 ocgroups x 2 tsegs; thread = (b,h,w), 2 oc
// =====================================================================
__global__ void __launch_bounds__(128) k_layer1(const float* __restrict__ w1) {
    __shared__ float sw[C1 * CIN * 25];
    for (int i = threadIdx.x; i < C1 * CIN * 25; i += blockDim.x) sw[i] = w1[i];
    __syncthreads();

    int bx = blockIdx.x;
    int pixblk = bx & 255;           // 256 pixel blocks
    int ocg    = (bx >> 8) & 3;     // 4 oc groups (2 oc each)
    int seg    = bx >> 10;          // 2 time segments

    int tid = pixblk * 128 + threadIdx.x;
    int w = tid % WW; int t1 = tid / WW;
    int h = t1 % HH;  int b = t1 / HH;
    int oc0 = ocg * 2;

    int kstart = seg ? WARM_BEG : 0;
    int kstore = seg ? SEG0_END : 0;
    int kend   = seg ? NCH      : SEG0_END;

    float a[2], r[2];
    a[0] = a[1] = r[0] = r[1] = 0.f;

    for (int k = kstart; k < kend; k++) {
        uint32_t bits[CIN * 25];
#pragma unroll
        for (int c = 0; c < CIN; c++)
#pragma unroll
            for (int dy = 0; dy < 5; dy++)
#pragma unroll
                for (int dx = 0; dx < 5; dx++) {
                    int hh = h + dy - 2, ww = w + dx - 2;
                    uint32_t v = 0;
                    if (hh >= 0 && hh < HH && ww >= 0 && ww < WW)
                        v = g_xbits[(((b * NCH + k) * CIN + c) * HH + hh) * WW + ww];
                    bits[(c * 5 + dy) * 5 + dx] = v;
                }
#pragma unroll 1
        for (int oo = 0; oo < 2; oo++) {
            int o = oc0 + oo;
            float sums[32];
#pragma unroll
            for (int j = 0; j < 32; j++) sums[j] = 0.f;
#pragma unroll
            for (int tp = 0; tp < CIN * 25; tp++) {
                float wv = sw[o * CIN * 25 + tp];
                uint32_t bw = bits[tp];
#pragma unroll
                for (int j = 0; j < 32; j++)
                    if (bw & (1u << j)) sums[j] += wv;
            }
            uint32_t sb = 0;
            float av = a[oo], rv = r[oo];
#pragma unroll
            for (int j = 0; j < 32; j++) {
                av = D1 * av + sums[j];
                float v = av + rv;
                bool hd = v >= 30.0f;
                sb |= hd ? (1u << j) : 0u;
                rv = D1 * rv - (hd ? 30.0f : 0.0f);
            }
            a[oo] = av; r[oo] = rv;
            if (k >= kstore)
                g_s1[(((b * NCH + k) * C1 + o) * HH + h) * WW + w] = sb;
        }
    }
}

// =====================================================================
// K2: layer 2.  u = IIR_2(conv3x3(s1bits)); spike(th=50, dref=D2)
// same decomposition as K1
// =====================================================================
__global__ void __launch_bounds__(128) k_layer2(const float* __restrict__ w2) {
    __shared__ float sw[C2 * C1 * 9];
    for (int i = threadIdx.x; i < C2 * C1 * 9; i += blockDim.x) sw[i] = w2[i];
    __syncthreads();

    int bx = blockIdx.x;
    int pixblk = bx & 255;
    int ocg    = (bx >> 8) & 3;
    int seg    = bx >> 10;

    int tid = pixblk * 128 + threadIdx.x;
    int w = tid % WW; int t1 = tid / WW;
    int h = t1 % HH;  int b = t1 / HH;
    int oc0 = ocg * 2;

    int kstart = seg ? WARM_BEG : 0;
    int kstore = seg ? SEG0_END : 0;
    int kend   = seg ? NCH      : SEG0_END;

    float a[2], r[2];
    a[0] = a[1] = r[0] = r[1] = 0.f;

    for (int k = kstart; k < kend; k++) {
        uint32_t bits[C1 * 9];
#pragma unroll
        for (int c = 0; c < C1; c++)
#pragma unroll
            for (int dy = 0; dy < 3; dy++)
#pragma unroll
                for (int dx = 0; dx < 3; dx++) {
                    int hh = h + dy - 1, ww = w + dx - 1;
                    uint32_t v = 0;
                    if (hh >= 0 && hh < HH && ww >= 0 && ww < WW)
                        v = g_s1[(((b * NCH + k) * C1 + c) * HH + hh) * WW + ww];
                    bits[(c * 3 + dy) * 3 + dx] = v;
                }
#pragma unroll 1
        for (int oo = 0; oo < 2; oo++) {
            int o = oc0 + oo;
            float sums[32];
#pragma unroll
            for (int j = 0; j < 32; j++) sums[j] = 0.f;
#pragma unroll
            for (int tp = 0; tp < C1 * 9; tp++) {
                float wv = sw[o * C1 * 9 + tp];
                uint32_t bw = bits[tp];
#pragma unroll
                for (int j = 0; j < 32; j++)
                    if (bw & (1u << j)) sums[j] += wv;
            }
            uint32_t sb = 0;
            float av = a[oo], rv = r[oo];
#pragma unroll
            for (int j = 0; j < 32; j++) {
                av = D2 * av + sums[j];
                float v = av + rv;
                bool hd = v >= 50.0f;
                sb |= hd ? (1u << j) : 0u;
                rv = D2 * rv - (hd ? 50.0f : 0.0f);
            }
            a[oo] = av; r[oo] = rv;
            if (k >= kstore)
                g_s2[(((b * NCH + k) * C2 + o) * HH + h) * WW + w] = sb;
        }
    }
}

// =====================================================================
// K3: layer 3.  u3 = IIR_4(convT2x2(s2bits)) + IIR_1(bilinear2x(xbits))
//               spike(th=100, dref=D3).  oc-split: thread = (b,ho,wo), 1 oc.
//   convT k=2 s=2: out[o, 2h+a, 2w+bb] += s2[c,h,w] * wup[o,c,1-a,1-bb]
//   bilinear taps: even -> (i-1:0.25, i:0.75), odd -> (i:0.75, i+1:0.25), clamped
// =====================================================================
__global__ void __launch_bounds__(128) k_layer3(const float* __restrict__ wup,
                                                float* __restrict__ out) {
    __shared__ float swu[64];
    if (threadIdx.x < 64) swu[threadIdx.x] = wup[threadIdx.x];
    __syncthreads();

    int bx = blockIdx.x;
    int o  = bx >> 10;               // output channel (2)
    int tid = (bx & 1023) * 128 + threadIdx.x;
    int wo = tid & 127; int t1 = tid >> 7;
    int ho = t1 & 127;  int b  = t1 >> 7;
    int hi = ho >> 1, wi = wo >> 1;
    int pa = ho & 1,  pb = wo & 1;

    int r0, r1, c0, c1; float wr0, wr1, wc0, wc1;
    if (!pa) { r0 = (hi > 0) ? hi - 1 : 0;  r1 = hi; wr0 = 0.25f; wr1 = 0.75f; }
    else     { r0 = hi; r1 = (hi < 63) ? hi + 1 : 63; wr0 = 0.75f; wr1 = 0.25f; }
    if (!pb) { c0 = (wi > 0) ? wi - 1 : 0;  c1 = wi; wc0 = 0.25f; wc1 = 0.75f; }
    else     { c0 = wi; c1 = (wi < 63) ? wi + 1 : 63; wc0 = 0.75f; wc1 = 0.25f; }
    float tw00 = wr0 * wc0, tw01 = wr0 * wc1, tw10 = wr1 * wc0, tw11 = wr1 * wc1;

    int lane = threadIdx.x & 31;
    int wo0  = wo & ~31;   // warp = 32 consecutive wo, same (b, ho)

    float av = 0.f, pv = 0.f, rv = 0.f;

    for (int k = 0; k < NCH; k++) {
        uint32_t s2b[C2];
#pragma unroll
        for (int c = 0; c < C2; c++)
            s2b[c] = g_s2[(((b * NCH + k) * C2 + c) * HH + hi) * WW + wi];
        const uint32_t* xp = g_xbits + (size_t)(((b * NCH + k) * CIN) + o) * HH * WW;
        uint32_t xb00 = xp[r0 * WW + c0], xb01 = xp[r0 * WW + c1];
        uint32_t xb10 = xp[r1 * WW + c0], xb11 = xp[r1 * WW + c1];

        float sA[32], sX[32];
#pragma unroll
        for (int j = 0; j < 32; j++) { sA[j] = 0.f; sX[j] = 0.f; }
#pragma unroll
        for (int c = 0; c < C2; c++) {
            float wv = swu[((o * 8 + c) * 2 + (1 - pa)) * 2 + (1 - pb)];
            uint32_t bw = s2b[c];
#pragma unroll
            for (int j = 0; j < 32; j++)
                if (bw & (1u << j)) sA[j] += wv;
        }
#pragma unroll
        for (int j = 0; j < 32; j++) if (xb00 & (1u << j)) sX[j] += tw00;
#pragma unroll
        for (int j = 0; j < 32; j++) if (xb01 & (1u << j)) sX[j] += tw01;
#pragma unroll
        for (int j = 0; j < 32; j++) if (xb10 & (1u << j)) sX[j] += tw10;
#pragma unroll
        for (int j = 0; j < 32; j++) if (xb11 & (1u << j)) sX[j] += tw11;

        uint32_t sb = 0;
#pragma unroll
        for (int j = 0; j < 32; j++) {
            av = D3 * av + sA[j];
            pv = D1 * pv + sX[j];
            float v = av + pv + rv;
            bool hd = v >= 100.0f;
            sb |= hd ? (1u << j) : 0u;
            rv = D3 * rv - (hd ? 100.0f : 0.0f);
        }

        // transposed coalesced store: lane writes t = 32k+lane of pixel (wo0+pl)
        size_t rowbase = ((size_t)((b * 2 + o) * 128 + ho) * 128 + wo0) * TT;
        int t = k * 32 + lane;
#pragma unroll
        for (int pl = 0; pl < 32; pl++) {
            uint32_t wv = __shfl_sync(0xffffffffu, sb, pl);
            if (t < TT)
                out[rowbase + (size_t)pl * TT + t] = ((wv >> lane) & 1u) ? 1.0f : 0.0f;
        }
    }
}

// =====================================================================
extern "C" void kernel_launch(void* const* d_in, const int* in_sizes, int n_in,
                              void* d_out, int out_size) {
    const float* x   = (const float*)d_in[0];
    const float* w1  = (const float*)d_in[1];
    const float* w2  = (const float*)d_in[2];
    const float* wup = (const float*)d_in[3];
    float* out = (float*)d_out;

    int n0 = BATCH * CIN * HH * WW * NCH;           // 458752
    k_binarize<<<(n0 + 255) / 256, 256>>>(x);
    k_layer1<<<256 * 4 * 2, 128>>>(w1);             // 2048 blocks
    k_layer2<<<256 * 4 * 2, 128>>>(w2);             // 2048 blocks
    k_layer3<<<1024 * 2, 128>>>(wup, out);          // 2048 blocks
}

// round 5
// speedup vs baseline: 1.6620x; 1.6620x over previous
#include <cuda_runtime.h>
#include <cuda_bf16.h>
#include <stdint.h>

// ---------------- problem dims ----------------
#define BATCH 8
#define CIN   2
#define HH    64
#define WW    64
#define TT    200
#define NCH   7      // ceil(200/32) chunks of 32 timesteps (tail garbage is causal-safe)
#define C1    8
#define C2    8
#define NTAP1 (CIN * 25)   // 50
#define NTAP2 (C1 * 9)     // 72

// fp32 correctly-rounded decay constants
#define D1 0.36787944117144233f   // exp(-1)    : tau=1 (psp1, ref1)
#define D2 0.60653065971263342f   // exp(-1/2)  : tau=2 (psp2, ref2)
#define D3 0.77880078307140487f   // exp(-1/4)  : tau=4 (psp3, ref3)

// ---------------- bit-packed intermediates ----------------
// layout: [b][chunk][c][h][w], one uint32 = 32 consecutive timesteps
__device__ uint32_t g_xbits[BATCH * NCH * CIN * HH * WW];  // 1.75 MB
__device__ uint32_t g_s1  [BATCH * NCH * C1  * HH * WW];   // 7 MB
__device__ uint32_t g_s2  [BATCH * NCH * C2  * HH * WW];   // 7 MB

// =====================================================================
// K0: binarize + time-transpose input [b,c,h,w,t] -> bitmasks
// =====================================================================
__global__ void k_binarize(const float* __restrict__ x) {
    int tid = blockIdx.x * blockDim.x + threadIdx.x;
    if (tid >= BATCH * CIN * HH * WW * NCH) return;
    int k   = tid % NCH;
    int pix = tid / NCH;
    int w = pix % WW; int t1 = pix / WW;
    int h = t1 % HH;  t1 /= HH;
    int c = t1 % CIN; int b = t1 / CIN;
    const float* p = x + (size_t)pix * TT + k * 32;
    int n = min(32, TT - k * 32);
    uint32_t bits = 0;
    for (int i = 0; i < n; i++) bits |= (p[i] > 0.5f) ? (1u << i) : 0u;
    g_xbits[(((b * NCH + k) * CIN + c) * HH + h) * WW + w] = bits;
}

// =====================================================================
// K1: layer 1.  u = IIR_1(conv5x5(xbits)); spike(th=30, dref=D1)
// thread = (b,h,w), ALL 8 oc. Predicate shared across oc: per tap-bit
// 1 test + 8 predicated FADD. j processed in 4 groups of 8 (reg wall).
// Accumulation order per (oc,j) identical to reference order -> bit-exact.
// =====================================================================
__global__ void __launch_bounds__(128) k_layer1(const float* __restrict__ w1) {
    __shared__ float swT[NTAP1 * 8];          // [tap][oc], 32B/row -> float4-aligned
    for (int i = threadIdx.x; i < NTAP1 * 8; i += blockDim.x) {
        int o = i & 7, tp = i >> 3;
        swT[i] = w1[o * NTAP1 + tp];
    }
    __syncthreads();

    int tid = blockIdx.x * blockDim.x + threadIdx.x;
    int w = tid % WW; int t1 = tid / WW;
    int h = t1 % HH;  int b = t1 / HH;

    float a[C1], r[C1];
#pragma unroll
    for (int o = 0; o < C1; o++) { a[o] = 0.f; r[o] = 0.f; }

    for (int k = 0; k < NCH; k++) {
        uint32_t bits[NTAP1];
#pragma unroll
        for (int c = 0; c < CIN; c++)
#pragma unroll
            for (int dy = 0; dy < 5; dy++)
#pragma unroll
                for (int dx = 0; dx < 5; dx++) {
                    int hh = h + dy - 2, ww = w + dx - 2;
                    uint32_t v = 0;
                    if (hh >= 0 && hh < HH && ww >= 0 && ww < WW)
                        v = g_xbits[(((b * NCH + k) * CIN + c) * HH + hh) * WW + ww];
                    bits[(c * 5 + dy) * 5 + dx] = v;
                }

        uint32_t sb[C1];
#pragma unroll
        for (int o = 0; o < C1; o++) sb[o] = 0u;

#pragma unroll 1
        for (int jg = 0; jg < 4; jg++) {
            float s[8 * 8];                    // [oc][jj]
#pragma unroll
            for (int i = 0; i < 64; i++) s[i] = 0.f;
#pragma unroll 1
            for (int tp = 0; tp < NTAP1; tp++) {
                uint32_t bw = bits[tp] >> (jg * 8);
                float4 wA = *(const float4*)&swT[tp * 8];
                float4 wB = *(const float4*)&swT[tp * 8 + 4];
#pragma unroll
                for (int jj = 0; jj < 8; jj++) {
                    if (bw & (1u << jj)) {
                        s[0 * 8 + jj] += wA.x; s[1 * 8 + jj] += wA.y;
                        s[2 * 8 + jj] += wA.z; s[3 * 8 + jj] += wA.w;
                        s[4 * 8 + jj] += wB.x; s[5 * 8 + jj] += wB.y;
                        s[6 * 8 + jj] += wB.z; s[7 * 8 + jj] += wB.w;
                    }
                }
            }
#pragma unroll
            for (int jj = 0; jj < 8; jj++) {
                int j = jg * 8 + jj;
#pragma unroll
                for (int o = 0; o < C1; o++) {
                    a[o] = D1 * a[o] + s[o * 8 + jj];
                    float v = a[o] + r[o];
                    bool hd = v >= 30.0f;
                    sb[o] |= hd ? (1u << j) : 0u;
                    r[o] = D1 * r[o] - (hd ? 30.0f : 0.0f);
                }
            }
        }
#pragma unroll
        for (int o = 0; o < C1; o++)
            g_s1[(((b * NCH + k) * C1 + o) * HH + h) * WW + w] = sb[o];
    }
}

// =====================================================================
// K2: layer 2.  u = IIR_2(conv3x3(s1bits)); spike(th=50, dref=D2)
// same predicate-sharing structure, 72 taps
// =====================================================================
__global__ void __launch_bounds__(128) k_layer2(const float* __restrict__ w2) {
    __shared__ float swT[NTAP2 * 8];
    for (int i = threadIdx.x; i < NTAP2 * 8; i += blockDim.x) {
        int o = i & 7, tp = i >> 3;
        swT[i] = w2[o * NTAP2 + tp];
    }
    __syncthreads();

    int tid = blockIdx.x * blockDim.x + threadIdx.x;
    int w = tid % WW; int t1 = tid / WW;
    int h = t1 % HH;  int b = t1 / HH;

    float a[C2], r[C2];
#pragma unroll
    for (int o = 0; o < C2; o++) { a[o] = 0.f; r[o] = 0.f; }

    for (int k = 0; k < NCH; k++) {
        uint32_t bits[NTAP2];
#pragma unroll
        for (int c = 0; c < C1; c++)
#pragma unroll
            for (int dy = 0; dy < 3; dy++)
#pragma unroll
                for (int dx = 0; dx < 3; dx++) {
                    int hh = h + dy - 1, ww = w + dx - 1;
                    uint32_t v = 0;
                    if (hh >= 0 && hh < HH && ww >= 0 && ww < WW)
                        v = g_s1[(((b * NCH + k) * C1 + c) * HH + hh) * WW + ww];
                    bits[(c * 3 + dy) * 3 + dx] = v;
                }

        uint32_t sb[C2];
#pragma unroll
        for (int o = 0; o < C2; o++) sb[o] = 0u;

#pragma unroll 1
        for (int jg = 0; jg < 4; jg++) {
            float s[8 * 8];
#pragma unroll
            for (int i = 0; i < 64; i++) s[i] = 0.f;
#pragma unroll 1
            for (int tp = 0; tp < NTAP2; tp++) {
                uint32_t bw = bits[tp] >> (jg * 8);
                float4 wA = *(const float4*)&swT[tp * 8];
                float4 wB = *(const float4*)&swT[tp * 8 + 4];
#pragma unroll
                for (int jj = 0; jj < 8; jj++) {
                    if (bw & (1u << jj)) {
                        s[0 * 8 + jj] += wA.x; s[1 * 8 + jj] += wA.y;
                        s[2 * 8 + jj] += wA.z; s[3 * 8 + jj] += wA.w;
                        s[4 * 8 + jj] += wB.x; s[5 * 8 + jj] += wB.y;
                        s[6 * 8 + jj] += wB.z; s[7 * 8 + jj] += wB.w;
                    }
                }
            }
#pragma unroll
            for (int jj = 0; jj < 8; jj++) {
                int j = jg * 8 + jj;
#pragma unroll
                for (int o = 0; o < C2; o++) {
                    a[o] = D2 * a[o] + s[o * 8 + jj];
                    float v = a[o] + r[o];
                    bool hd = v >= 50.0f;
                    sb[o] |= hd ? (1u << j) : 0u;
                    r[o] = D2 * r[o] - (hd ? 50.0f : 0.0f);
                }
            }
        }
#pragma unroll
        for (int o = 0; o < C2; o++)
            g_s2[(((b * NCH + k) * C2 + o) * HH + h) * WW + w] = sb[o];
    }
}

// =====================================================================
// K3: layer 3 (unchanged from R3 — known 84.5us).
//   u3 = IIR_4(convT2x2(s2bits)) + IIR_1(bilinear2x(xbits)); spike(th=100, dref=D3)
// =====================================================================
__global__ void __launch_bounds__(128) k_layer3(const float* __restrict__ wup,
                                                float* __restrict__ out) {
    __shared__ float swu[64];
    if (threadIdx.x < 64) swu[threadIdx.x] = wup[threadIdx.x];
    __syncthreads();

    int tid = blockIdx.x * blockDim.x + threadIdx.x;
    int wo = tid & 127; int t1 = tid >> 7;
    int ho = t1 & 127;  int b  = t1 >> 7;
    int hi = ho >> 1, wi = wo >> 1;
    int pa = ho & 1,  pb = wo & 1;

    int r0, r1, c0, c1; float wr0, wr1, wc0, wc1;
    if (!pa) { r0 = (hi > 0) ? hi - 1 : 0;  r1 = hi; wr0 = 0.25f; wr1 = 0.75f; }
    else     { r0 = hi; r1 = (hi < 63) ? hi + 1 : 63; wr0 = 0.75f; wr1 = 0.25f; }
    if (!pb) { c0 = (wi > 0) ? wi - 1 : 0;  c1 = wi; wc0 = 0.25f; wc1 = 0.75f; }
    else     { c0 = wi; c1 = (wi < 63) ? wi + 1 : 63; wc0 = 0.75f; wc1 = 0.25f; }
    float tw00 = wr0 * wc0, tw01 = wr0 * wc1, tw10 = wr1 * wc0, tw11 = wr1 * wc1;

    int lane = threadIdx.x & 31;
    int wo0  = wo & ~31;

    float a[2], p[2], rr[2];
#pragma unroll
    for (int o = 0; o < 2; o++) { a[o] = 0.f; p[o] = 0.f; rr[o] = 0.f; }

    for (int k = 0; k < NCH; k++) {
        uint32_t s2b[C2];
#pragma unroll
        for (int c = 0; c < C2; c++)
            s2b[c] = g_s2[(((b * NCH + k) * C2 + c) * HH + hi) * WW + wi];
        uint32_t xb00[2], xb01[2], xb10[2], xb11[2];
#pragma unroll
        for (int c = 0; c < 2; c++) {
            const uint32_t* xp = g_xbits + (size_t)(((b * NCH + k) * CIN) + c) * HH * WW;
            xb00[c] = xp[r0 * WW + c0]; xb01[c] = xp[r0 * WW + c1];
            xb10[c] = xp[r1 * WW + c0]; xb11[c] = xp[r1 * WW + c1];
        }
#pragma unroll 1
        for (int o = 0; o < 2; o++) {
            float sA[32], sX[32];
#pragma unroll
            for (int j = 0; j < 32; j++) { sA[j] = 0.f; sX[j] = 0.f; }
#pragma unroll
            for (int c = 0; c < C2; c++) {
                float wv = swu[((o * 8 + c) * 2 + (1 - pa)) * 2 + (1 - pb)];
                uint32_t bw = s2b[c];
#pragma unroll
                for (int j = 0; j < 32; j++)
                    if (bw & (1u << j)) sA[j] += wv;
            }
            {
                uint32_t bw = xb00[o];
#pragma unroll
                for (int j = 0; j < 32; j++) if (bw & (1u << j)) sX[j] += tw00;
            }
            {
                uint32_t bw = xb01[o];
#pragma unroll
                for (int j = 0; j < 32; j++) if (bw & (1u << j)) sX[j] += tw01;
            }
            {
                uint32_t bw = xb10[o];
#pragma unroll
                for (int j = 0; j < 32; j++) if (bw & (1u << j)) sX[j] += tw10;
            }
            {
                uint32_t bw = xb11[o];
#pragma unroll
                for (int j = 0; j < 32; j++) if (bw & (1u << j)) sX[j] += tw11;
            }
            uint32_t sb = 0;
            float av = a[o], pv = p[o], rv = rr[o];
#pragma unroll
            for (int j = 0; j < 32; j++) {
                av = D3 * av + sA[j];
                pv = D1 * pv + sX[j];
                float v = av + pv + rv;
                bool hd = v >= 100.0f;
                sb |= hd ? (1u << j) : 0u;
                rv = D3 * rv - (hd ? 100.0f : 0.0f);
            }
            a[o] = av; p[o] = pv; rr[o] = rv;

            size_t rowbase = ((size_t)((b * 2 + o) * 128 + ho) * 128 + wo0) * TT;
            int t = k * 32 + lane;
#pragma unroll
            for (int pl = 0; pl < 32; pl++) {
                uint32_t wv = __shfl_sync(0xffffffffu, sb, pl);
                if (t < TT)
                    out[rowbase + (size_t)pl * TT + t] = ((wv >> lane) & 1u) ? 1.0f : 0.0f;
            }
        }
    }
}

// =====================================================================
extern "C" void kernel_launch(void* const* d_in, const int* in_sizes, int n_in,
                              void* d_out, int out_size) {
    const float* x   = (const float*)d_in[0];
    const float* w1  = (const float*)d_in[1];
    const float* w2  = (const float*)d_in[2];
    const float* wup = (const float*)d_in[3];
    float* out = (float*)d_out;

    int n0 = BATCH * CIN * HH * WW * NCH;
    k_binarize<<<(n0 + 255) / 256, 256>>>(x);
    k_layer1<<<(BATCH * HH * WW) / 128, 128>>>(w1);     // 256 blocks
    k_layer2<<<(BATCH * HH * WW) / 128, 128>>>(w2);     // 256 blocks
    k_layer3<<<(BATCH * 128 * 128) / 128, 128>>>(wup, out); // 1024 blocks
}